// round 16
// baseline (speedup 1.0000x reference)
#include <cuda_runtime.h>
#include <cuda_bf16.h>
#include <math.h>
#include <stdint.h>

#define NN 50000
#define EE 800000
#define EPE 850000               /* EE + NN self loops */
#define TILES 391                /* ceil(50000/128) */
#define NPAD (TILES * 128)       /* 50048 */
#define MAXDEG 128
#define AGG_BLOCKS 6250          /* 50000 warps / 8 */
#define SCAT_BLOCKS 3321         /* ceil(850000/256) */
#define CLEAN_BLOCKS 196         /* ceil(50000/256) */

// ---------------- scratch (static device memory) ---------------------------
__device__ int    g_cnt[NN];                       // zeroed in launch 1
__device__ int    g_srcs[(size_t)NN * MAXDEG];
__device__ __align__(16) float2 g_as[NN];
__device__ __align__(16) float2 g_ad[NN];
__device__ __align__(16) float  g_ps[2][256];
__device__ __align__(16) float  g_pd[2][256];
__device__ __align__(16) float  g_xbuf[(size_t)NN * 128];
__device__ __align__(16) __nv_bfloat16 g_ah[(size_t)NPAD * 256];     // A hi
__device__ __align__(16) __nv_bfloat16 g_al[(size_t)NPAD * 256];     // A lo
__device__ __align__(16) __nv_bfloat16 g_Wh[2][128 * 256];           // B hi [n][k]
__device__ __align__(16) __nv_bfloat16 g_Wl[2][128 * 256];           // B lo

// ---------------- helpers ----------------------------------------------------
typedef unsigned long long ull;
union F4U {
    float4 f;
    struct { ull lo, hi; } u;
};
__device__ __forceinline__ void fma2(ull& d, ull a, ull b) {
    asm("fma.rn.f32x2 %0, %1, %2, %0;" : "+l"(d) : "l"(a), "l"(b));
}
__device__ __forceinline__ uint32_t smem_u32(const void* p) {
    uint32_t a;
    asm("{ .reg .u64 t; cvta.to.shared.u64 t, %1; cvt.u32.u64 %0, t; }"
        : "=r"(a) : "l"(p));
    return a;
}
__device__ __forceinline__ void ldsm_x4(uint32_t* r, uint32_t addr) {
    asm volatile("ldmatrix.sync.aligned.m8n8.x4.shared.b16 {%0,%1,%2,%3}, [%4];"
                 : "=r"(r[0]), "=r"(r[1]), "=r"(r[2]), "=r"(r[3]) : "r"(addr));
}
__device__ __forceinline__ void ldsm_x2(uint32_t* r, uint32_t addr) {
    asm volatile("ldmatrix.sync.aligned.m8n8.x2.shared.b16 {%0,%1}, [%2];"
                 : "=r"(r[0]), "=r"(r[1]) : "r"(addr));
}
__device__ __forceinline__ void mma16816(float* c, const uint32_t* a, const uint32_t* b) {
    asm volatile("mma.sync.aligned.m16n8k16.row.col.f32.bf16.bf16.f32 "
                 "{%0,%1,%2,%3}, {%4,%5,%6,%7}, {%8,%9}, {%0,%1,%2,%3};"
                 : "+f"(c[0]), "+f"(c[1]), "+f"(c[2]), "+f"(c[3])
                 : "r"(a[0]), "r"(a[1]), "r"(a[2]), "r"(a[3]),
                   "r"(b[0]), "r"(b[1]));
}
__device__ __forceinline__ void cpasync16(uint32_t dst, const void* src) {
    asm volatile("cp.async.ca.shared.global [%0], [%1], 16;" :: "r"(dst), "l"(src));
}
#define CP_COMMIT() asm volatile("cp.async.commit_group;" ::: "memory")

// ---------------- launch 1: cleanup + both layers' weight prep --------------
__global__ void prep_clean_kernel(const float* __restrict__ W,
                                  const float* __restrict__ asrc,
                                  const float* __restrict__ adst) {
    int b = blockIdx.x, tid = threadIdx.x;
    if (b < CLEAN_BLOCKS) {
        int i = b * 256 + tid;
        if (i < NN) g_cnt[i] = 0;
        return;
    }
    int q = b - CLEAN_BLOCKS;
    int layer = q / 132;
    int r = q % 132;
    const float* Wl = W + (size_t)layer * 128 * 256;
    if (r < 128) {
        int k = tid;                       // 0..255
        int h = k >> 7, j = k & 127;
        float v = 0.5f * Wl[(size_t)j * 256 + h * 128 + r];
        __nv_bfloat16 hi = __float2bfloat16(v);
        g_Wh[layer][r * 256 + k] = hi;
        g_Wl[layer][r * 256 + k] = __float2bfloat16(v - __bfloat162float(hi));
    } else if (tid < 128) {
        int qq = r - 128;
        int h = qq & 1, typ = qq >> 1;     // 0 = src, 1 = dst
        const float* att = (typ ? adst : asrc) + layer * 256 + h * 128;
        const float* Wr  = Wl + (size_t)tid * 256 + h * 128;
        float sum = 0.f;
#pragma unroll 8
        for (int j = 0; j < 128; j++) sum += Wr[j] * att[j];
        (typ ? g_pd : g_ps)[layer][h * 128 + tid] = sum;
    }
}

// ---------------- fused alpha(layer0) + capacity-slotted scatter ------------
__device__ __forceinline__ void alpha_body(const float* __restrict__ x,
                                           int w, int lane) {
    float4 xv = *(const float4*)(x + (size_t)w * 128 + lane * 4);
    float4 p;
    p = *(const float4*)(&g_ps[0][lane * 4]);
    float s0 = xv.x * p.x + xv.y * p.y + xv.z * p.z + xv.w * p.w;
    p = *(const float4*)(&g_ps[0][128 + lane * 4]);
    float s1 = xv.x * p.x + xv.y * p.y + xv.z * p.z + xv.w * p.w;
    p = *(const float4*)(&g_pd[0][lane * 4]);
    float d0 = xv.x * p.x + xv.y * p.y + xv.z * p.z + xv.w * p.w;
    p = *(const float4*)(&g_pd[0][128 + lane * 4]);
    float d1 = xv.x * p.x + xv.y * p.y + xv.z * p.z + xv.w * p.w;
#pragma unroll
    for (int o = 16; o; o >>= 1) {
        s0 += __shfl_xor_sync(0xffffffffu, s0, o);
        s1 += __shfl_xor_sync(0xffffffffu, s1, o);
        d0 += __shfl_xor_sync(0xffffffffu, d0, o);
        d1 += __shfl_xor_sync(0xffffffffu, d1, o);
    }
    if (lane == 0) {
        g_as[w] = make_float2(s0, s1);
        g_ad[w] = make_float2(d0, d1);
    }
}

__global__ void __launch_bounds__(256) alpha_scatter_kernel(const float* __restrict__ x,
                                                            const int* __restrict__ ei) {
    int b = blockIdx.x;
    if (b < AGG_BLOCKS) {
        int w = (b * 256 + threadIdx.x) >> 5;
        if (w < NN) alpha_body(x, w, threadIdx.x & 31);
    } else {
        int i = (b - AGG_BLOCKS) * 256 + threadIdx.x;
        if (i >= EPE) return;
        int src, dst;
        if (i < EE) { src = ei[i]; dst = ei[EE + i]; }
        else        { src = i - EE; dst = i - EE; }
        src = min(max(src, 0), NN - 1);
        dst = min(max(dst, 0), NN - 1);
        int pos = atomicAdd(&g_cnt[dst], 1);
        if (pos < MAXDEG) g_srcs[(size_t)dst * MAXDEG + pos] = src;
    }
}

// ---------------- edge aggregation (warp per node, smem-staged weights) -----
__device__ __forceinline__ uint32_t pack_split(float a, float b, uint32_t& lo) {
    __nv_bfloat16 ha = __float2bfloat16(a), hb = __float2bfloat16(b);
    __nv_bfloat16 la = __float2bfloat16(a - __bfloat162float(ha));
    __nv_bfloat16 lb = __float2bfloat16(b - __bfloat162float(hb));
    lo = (uint32_t)__bfloat16_as_ushort(la) | ((uint32_t)__bfloat16_as_ushort(lb) << 16);
    return (uint32_t)__bfloat16_as_ushort(ha) | ((uint32_t)__bfloat16_as_ushort(hb) << 16);
}

__global__ void __launch_bounds__(256) aggregate_kernel(const float* __restrict__ x) {
    int node = (blockIdx.x * blockDim.x + threadIdx.x) >> 5;
    if (node >= NN) return;
    const int lane = threadIdx.x & 31;
    const int ww = (threadIdx.x >> 5) & 7;

    __shared__ __align__(16) float4 st_w[8][32];
    __shared__ int st_s[8][32];

    const int deg = min(g_cnt[node], MAXDEG);
    const int* srcs = g_srcs + (size_t)node * MAXDEG;
    const float2 adv = g_ad[node];

    float w0 = 0.f, w1 = 0.f;
    int sj = 0;
    if (lane < deg) {
        sj = srcs[lane];
        float2 a = g_as[sj];
        float e0 = a.x + adv.x;  e0 = e0 > 0.f ? e0 : 0.2f * e0;
        float e1 = a.y + adv.y;  e1 = e1 > 0.f ? e1 : 0.2f * e1;
        w0 = __expf(e0);
        w1 = __expf(e1);
    }
    float s0 = w0, s1 = w1;
    for (int e = 32 + lane; e < deg; e += 32) {
        float2 a = g_as[srcs[e]];
        float e0 = a.x + adv.x;  e0 = e0 > 0.f ? e0 : 0.2f * e0;
        float e1 = a.y + adv.y;  e1 = e1 > 0.f ? e1 : 0.2f * e1;
        s0 += __expf(e0);
        s1 += __expf(e1);
    }
#pragma unroll
    for (int o = 16; o; o >>= 1) {
        s0 += __shfl_xor_sync(0xffffffffu, s0, o);
        s1 += __shfl_xor_sync(0xffffffffu, s1, o);
    }

    ull a00 = 0ull, a01 = 0ull, a10 = 0ull, a11 = 0ull;
    const float* xb = x + lane * 4;

    for (int base = 0; base < deg; base += 32) {
        if (base) {                         // recompute only for deg>32 (rare)
            w0 = w1 = 0.f;
            sj = 0;
            if (base + lane < deg) {
                sj = srcs[base + lane];
                float2 a = g_as[sj];
                float e0 = a.x + adv.x;  e0 = e0 > 0.f ? e0 : 0.2f * e0;
                float e1 = a.y + adv.y;  e1 = e1 > 0.f ? e1 : 0.2f * e1;
                w0 = __expf(e0);
                w1 = __expf(e1);
            }
        }
        st_w[ww][lane] = make_float4(w0, w0, w1, w1);
        st_s[ww][lane] = sj;
        __syncwarp();
        int nn = min(32, deg - base);
#pragma unroll 2
        for (int i = 0; i < nn; i++) {
            int s = st_s[ww][i];
            F4U w; w.f = st_w[ww][i];
            F4U v; v.f = *(const float4*)(xb + (size_t)s * 128);
            fma2(a00, w.u.lo, v.u.lo);
            fma2(a01, w.u.lo, v.u.hi);
            fma2(a10, w.u.hi, v.u.lo);
            fma2(a11, w.u.hi, v.u.hi);
        }
        __syncwarp();
    }

    float i0 = 1.f / (s0 + 1e-16f);
    float i1 = 1.f / (s1 + 1e-16f);
    F4U r0, r1;
    r0.u.lo = a00; r0.u.hi = a01;
    r1.u.lo = a10; r1.u.hi = a11;

    uint2 h0, l0, h1, l1;
    h0.x = pack_split(r0.f.x * i0, r0.f.y * i0, l0.x);
    h0.y = pack_split(r0.f.z * i0, r0.f.w * i0, l0.y);
    h1.x = pack_split(r1.f.x * i1, r1.f.y * i1, l1.x);
    h1.y = pack_split(r1.f.z * i1, r1.f.w * i1, l1.y);
    size_t o = (size_t)node * 256 + lane * 4;
    *(uint2*)(g_ah + o)       = h0;
    *(uint2*)(g_al + o)       = l0;
    *(uint2*)(g_ah + o + 128) = h1;
    *(uint2*)(g_al + o + 128) = l1;
}

// ---------------- HMMA GEMM: 3-stage cp.async pipeline, swizzled tiles -------
// Tile = 128 rows x 64B (no padding); quad q swizzled by (row & 3):
//   off(r, q) = r*64 + ((q ^ (r & 3)) * 16)
// Stage = 4 tiles x 8192B = 32KB; 3 stages; ONE __syncthreads per K-chunk.
#define T_AH 0
#define T_AL 8192
#define T_BH 16384
#define T_BL 24576
#define STAGE 32768
#define OFF_SQ   (3 * STAGE)
#define OFF_P    (3 * STAGE + 512)
#define OFF_AACC (3 * STAGE + 2560)
#define SMEM_GEMM (3 * STAGE + 4608)

__device__ __forceinline__ void gemm_issue_load(uint32_t sb, int m0, int kc, int tid,
                                                const __nv_bfloat16* Wh,
                                                const __nv_bfloat16* Wl) {
#pragma unroll
    for (int it = 0; it < 2; it++) {
        int i = tid + it * 256;
        int r = i >> 2, kq = i & 3;
        uint32_t soff = (uint32_t)(r * 64 + ((kq ^ (r & 3)) * 16));
        size_t ga = (size_t)(m0 + r) * 256 + kc * 32 + kq * 8;
        size_t gb = (size_t)r * 256 + kc * 32 + kq * 8;
        cpasync16(sb + T_AH + soff, g_ah + ga);
        cpasync16(sb + T_AL + soff, g_al + ga);
        cpasync16(sb + T_BH + soff, Wh + gb);
        cpasync16(sb + T_BL + soff, Wl + gb);
    }
}

__global__ void __launch_bounds__(256, 2) gemm_hmma_kernel(const float* __restrict__ bias,
                                                           float* __restrict__ out,
                                                           int layer, int do_alpha) {
    extern __shared__ __align__(16) char sm[];
    const int tid = threadIdx.x, lane = tid & 31, wid = tid >> 5;
    const int wm = wid >> 2, wn = wid & 3;     // warp grid 2 x 4
    const int m0 = blockIdx.x * 128;
    const uint32_t sbase = smem_u32(sm);
    const __nv_bfloat16* Wh = g_Wh[layer];
    const __nv_bfloat16* Wl = g_Wl[layer];

    float* sq   = (float*)(sm + OFF_SQ);
    float* pb   = (float*)(sm + OFF_P);     // [512]: ps(256), pd(256) for layer 1
    float* aacc = (float*)(sm + OFF_AACC);  // [512]: as0, as1, ad0, ad1

    if (tid < 128) sq[tid] = 0.f;
    if (do_alpha) {
        pb[tid]       = g_ps[1][tid];
        pb[256 + tid] = g_pd[1][tid];
        aacc[tid]       = 0.f;
        aacc[256 + tid] = 0.f;
    }

    float acc[4][4][4];
#pragma unroll
    for (int a = 0; a < 4; a++)
#pragma unroll
        for (int b = 0; b < 4; b++)
#pragma unroll
            for (int c = 0; c < 4; c++) acc[a][b][c] = 0.f;

    // per-lane swizzled ldsm offsets: row&3 folds to lane constants
    const int rA = lane & 15, kA = (lane >> 4) & 1;
    const uint32_t offA0 = (uint32_t)(rA * 64 + (((kA + 0) ^ (rA & 3)) * 16));
    const uint32_t offA1 = (uint32_t)(rA * 64 + (((kA + 2) ^ (rA & 3)) * 16));
    const int rB = lane & 7, kB = (lane >> 3) & 1;
    const uint32_t offB0 = (uint32_t)(rB * 64 + (((kB + 0) ^ (rB & 3)) * 16));
    const uint32_t offB1 = (uint32_t)(rB * 64 + (((kB + 2) ^ (rB & 3)) * 16));

    gemm_issue_load(sbase, m0, 0, tid, Wh, Wl);
    CP_COMMIT();
    gemm_issue_load(sbase + STAGE, m0, 1, tid, Wh, Wl);
    CP_COMMIT();

    int cur = 0, nxt2 = 2;
    for (int kc = 0; kc < 8; kc++) {
        if (kc < 7) {
            asm volatile("cp.async.wait_group 1;" ::: "memory");
        } else {
            asm volatile("cp.async.wait_group 0;" ::: "memory");
        }
        __syncthreads();
        if (kc + 2 < 8) {
            gemm_issue_load(sbase + nxt2 * STAGE, m0, kc + 2, tid, Wh, Wl);
            CP_COMMIT();
        }

        const uint32_t stg = sbase + cur * STAGE;
#pragma unroll
        for (int s = 0; s < 2; s++) {
            const uint32_t oA = s ? offA1 : offA0;
            const uint32_t oB = s ? offB1 : offB0;
            uint32_t ah[4][4], al[4][4], bh[4][2], bl[4][2];
#pragma unroll
            for (int mi = 0; mi < 4; mi++) {
                uint32_t a = oA + (uint32_t)(wm * 4096 + mi * 1024);
                ldsm_x4(ah[mi], stg + T_AH + a);
                ldsm_x4(al[mi], stg + T_AL + a);
            }
#pragma unroll
            for (int nj = 0; nj < 4; nj++) {
                uint32_t b = oB + (uint32_t)(wn * 2048 + nj * 512);
                ldsm_x2(bh[nj], stg + T_BH + b);
                ldsm_x2(bl[nj], stg + T_BL + b);
            }
#pragma unroll
            for (int mi = 0; mi < 4; mi++)
#pragma unroll
                for (int nj = 0; nj < 4; nj++) {
                    mma16816(acc[mi][nj], ah[mi], bh[nj]);
                    mma16816(acc[mi][nj], ah[mi], bl[nj]);
                    mma16816(acc[mi][nj], al[mi], bh[nj]);
                }
        }
        cur = (cur == 2) ? 0 : cur + 1;
        nxt2 = (nxt2 == 2) ? 0 : nxt2 + 1;
    }
    __syncthreads();   // protect epilogue smem (sq/aacc) vs last compute

    const int groupl = lane >> 2, qid = lane & 3;
    float2 bv[4];
#pragma unroll
    for (int nj = 0; nj < 4; nj++)
        bv[nj] = *(const float2*)(bias + wn * 32 + nj * 8 + qid * 2);

#pragma unroll
    for (int mi = 0; mi < 4; mi++) {
        float s1 = 0.f, s2 = 0.f;
#pragma unroll
        for (int nj = 0; nj < 4; nj++) {
            acc[mi][nj][0] += bv[nj].x;
            acc[mi][nj][1] += bv[nj].y;
            acc[mi][nj][2] += bv[nj].x;
            acc[mi][nj][3] += bv[nj].y;
            s1 += acc[mi][nj][0] * acc[mi][nj][0] + acc[mi][nj][1] * acc[mi][nj][1];
            s2 += acc[mi][nj][2] * acc[mi][nj][2] + acc[mi][nj][3] * acc[mi][nj][3];
        }
        s1 += __shfl_xor_sync(0xffffffffu, s1, 1);
        s1 += __shfl_xor_sync(0xffffffffu, s1, 2);
        s2 += __shfl_xor_sync(0xffffffffu, s2, 1);
        s2 += __shfl_xor_sync(0xffffffffu, s2, 2);
        if (qid == 0) {
            atomicAdd(&sq[wm * 64 + mi * 16 + groupl], s1);
            atomicAdd(&sq[wm * 64 + mi * 16 + groupl + 8], s2);
        }
    }
    __syncthreads();
    if (tid < 128) {
        float v = sq[tid];
        sq[tid] = 1.f / fmaxf(sqrtf(v), 1e-12f);
    }
    __syncthreads();

#pragma unroll
    for (int mi = 0; mi < 4; mi++) {
        int lr1 = wm * 64 + mi * 16 + groupl;
        int lr2 = lr1 + 8;
        float i1 = sq[lr1], i2 = sq[lr2];
        int r1 = m0 + lr1, r2 = m0 + lr2;
        float as0_1 = 0.f, as1_1 = 0.f, ad0_1 = 0.f, ad1_1 = 0.f;
        float as0_2 = 0.f, as1_2 = 0.f, ad0_2 = 0.f, ad1_2 = 0.f;
#pragma unroll
        for (int nj = 0; nj < 4; nj++) {
            int col = wn * 32 + nj * 8 + qid * 2;
            float v0 = acc[mi][nj][0] * i1, v1 = acc[mi][nj][1] * i1;
            float v2 = acc[mi][nj][2] * i2, v3 = acc[mi][nj][3] * i2;
            if (r1 < NN)
                *(float2*)(out + (size_t)r1 * 128 + col) = make_float2(v0, v1);
            if (r2 < NN)
                *(float2*)(out + (size_t)r2 * 128 + col) = make_float2(v2, v3);
            if (do_alpha) {
                float pa = pb[col],       pab = pb[col + 1];
                float qa = pb[128 + col], qab = pb[129 + col];
                float ra = pb[256 + col], rab = pb[257 + col];
                float ta = pb[384 + col], tab = pb[385 + col];
                as0_1 += pa * v0 + pab * v1;  as1_1 += qa * v0 + qab * v1;
                ad0_1 += ra * v0 + rab * v1;  ad1_1 += ta * v0 + tab * v1;
                as0_2 += pa * v2 + pab * v3;  as1_2 += qa * v2 + qab * v3;
                ad0_2 += ra * v2 + rab * v3;  ad1_2 += ta * v2 + tab * v3;
            }
        }
        if (do_alpha) {
#pragma unroll
            for (int o = 1; o < 4; o <<= 1) {
                as0_1 += __shfl_xor_sync(0xffffffffu, as0_1, o);
                as1_1 += __shfl_xor_sync(0xffffffffu, as1_1, o);
                ad0_1 += __shfl_xor_sync(0xffffffffu, ad0_1, o);
                ad1_1 += __shfl_xor_sync(0xffffffffu, ad1_1, o);
                as0_2 += __shfl_xor_sync(0xffffffffu, as0_2, o);
                as1_2 += __shfl_xor_sync(0xffffffffu, as1_2, o);
                ad0_2 += __shfl_xor_sync(0xffffffffu, ad0_2, o);
                ad1_2 += __shfl_xor_sync(0xffffffffu, ad1_2, o);
            }
            if (qid == 0) {
                atomicAdd(&aacc[lr1],       as0_1);
                atomicAdd(&aacc[128 + lr1], as1_1);
                atomicAdd(&aacc[256 + lr1], ad0_1);
                atomicAdd(&aacc[384 + lr1], ad1_1);
                atomicAdd(&aacc[lr2],       as0_2);
                atomicAdd(&aacc[128 + lr2], as1_2);
                atomicAdd(&aacc[256 + lr2], ad0_2);
                atomicAdd(&aacc[384 + lr2], ad1_2);
            }
        }
    }
    if (do_alpha) {
        __syncthreads();
        if (tid < 128) {
            int row = m0 + tid;
            if (row < NN) {
                g_as[row] = make_float2(aacc[tid], aacc[128 + tid]);
                g_ad[row] = make_float2(aacc[256 + tid], aacc[384 + tid]);
            }
        }
    }
}

// ---------------- launch ----------------------------------------------------
extern "C" void kernel_launch(void* const* d_in, const int* in_sizes, int n_in,
                              void* d_out, int out_size) {
    const float* x    = (const float*)d_in[0];
    const int*   ei   = (const int*)d_in[1];
    const float* W    = (const float*)d_in[2];
    const float* asrc = (const float*)d_in[3];
    const float* adst = (const float*)d_in[4];
    const float* bias = (const float*)d_in[5];
    float*       out  = (float*)d_out;

    void* xbuf_p = nullptr;
    cudaGetSymbolAddress(&xbuf_p, g_xbuf);
    float* xbuf = (float*)xbuf_p;

    cudaFuncSetAttribute(gemm_hmma_kernel,
                         cudaFuncAttributeMaxDynamicSharedMemorySize, SMEM_GEMM);

    // slots: prep_clean=1, alpha_scatter=2, agg0=3, gemm0=4 (profiled, +alpha1),
    //        agg1=5, gemm1=6
    prep_clean_kernel<<<CLEAN_BLOCKS + 264, 256>>>(W, asrc, adst);
    alpha_scatter_kernel<<<AGG_BLOCKS + SCAT_BLOCKS, 256>>>(x, ei);
    aggregate_kernel<<<AGG_BLOCKS, 256>>>(x);
    gemm_hmma_kernel<<<TILES, 256, SMEM_GEMM>>>(bias, xbuf, 0, 1);

    aggregate_kernel<<<AGG_BLOCKS, 256>>>(xbuf);
    gemm_hmma_kernel<<<TILES, 256, SMEM_GEMM>>>(bias + 128, out, 1, 0);
}

// round 17
// speedup vs baseline: 1.0954x; 1.0954x over previous
#include <cuda_runtime.h>
#include <cuda_bf16.h>
#include <math.h>
#include <stdint.h>

#define NN 50000
#define EE 800000
#define EPE 850000               /* EE + NN self loops */
#define TILES 391                /* ceil(50000/128) */
#define NPAD (TILES * 128)       /* 50048 */
#define MAXDEG 128
#define AGG_BLOCKS 6250          /* 50000 warps / 8 */
#define SCAT_BLOCKS 3321         /* ceil(850000/256) */
#define CLEAN_BLOCKS 196         /* ceil(50000/256) */

// ---------------- scratch (static device memory) ---------------------------
__device__ int    g_cnt[NN];                       // zeroed in launch 1
__device__ int    g_srcs[(size_t)NN * MAXDEG];
__device__ __align__(16) float2 g_as[NN];
__device__ __align__(16) float2 g_ad[NN];
__device__ __align__(16) float  g_ps[2][256];
__device__ __align__(16) float  g_pd[2][256];
__device__ __align__(16) float  g_xbuf[(size_t)NN * 128];
__device__ __align__(16) __nv_bfloat16 g_ah[(size_t)NPAD * 256];     // A hi
__device__ __align__(16) __nv_bfloat16 g_al[(size_t)NPAD * 256];     // A lo
__device__ __align__(16) __nv_bfloat16 g_Wh[2][128 * 256];           // B hi [n][k]
__device__ __align__(16) __nv_bfloat16 g_Wl[2][128 * 256];           // B lo

// ---------------- helpers ----------------------------------------------------
typedef unsigned long long ull;
union F4U {
    float4 f;
    struct { ull lo, hi; } u;
};
__device__ __forceinline__ void fma2(ull& d, ull a, ull b) {
    asm("fma.rn.f32x2 %0, %1, %2, %0;" : "+l"(d) : "l"(a), "l"(b));
}
__device__ __forceinline__ uint32_t smem_u32(const void* p) {
    uint32_t a;
    asm("{ .reg .u64 t; cvta.to.shared.u64 t, %1; cvt.u32.u64 %0, t; }"
        : "=r"(a) : "l"(p));
    return a;
}
__device__ __forceinline__ void ldsm_x4(uint32_t* r, uint32_t addr) {
    asm volatile("ldmatrix.sync.aligned.m8n8.x4.shared.b16 {%0,%1,%2,%3}, [%4];"
                 : "=r"(r[0]), "=r"(r[1]), "=r"(r[2]), "=r"(r[3]) : "r"(addr));
}
__device__ __forceinline__ void ldsm_x2(uint32_t* r, uint32_t addr) {
    asm volatile("ldmatrix.sync.aligned.m8n8.x2.shared.b16 {%0,%1}, [%2];"
                 : "=r"(r[0]), "=r"(r[1]) : "r"(addr));
}
__device__ __forceinline__ void mma16816(float* c, const uint32_t* a, const uint32_t* b) {
    asm volatile("mma.sync.aligned.m16n8k16.row.col.f32.bf16.bf16.f32 "
                 "{%0,%1,%2,%3}, {%4,%5,%6,%7}, {%8,%9}, {%0,%1,%2,%3};"
                 : "+f"(c[0]), "+f"(c[1]), "+f"(c[2]), "+f"(c[3])
                 : "r"(a[0]), "r"(a[1]), "r"(a[2]), "r"(a[3]),
                   "r"(b[0]), "r"(b[1]));
}
__device__ __forceinline__ void cpasync16(uint32_t dst, const void* src) {
    asm volatile("cp.async.ca.shared.global [%0], [%1], 16;" :: "r"(dst), "l"(src));
}
#define CP_COMMIT() asm volatile("cp.async.commit_group;" ::: "memory")

// ---------------- launch 1: cleanup + both layers' weight prep --------------
__global__ void prep_clean_kernel(const float* __restrict__ W,
                                  const float* __restrict__ asrc,
                                  const float* __restrict__ adst) {
    int b = blockIdx.x, tid = threadIdx.x;
    if (b < CLEAN_BLOCKS) {
        int i = b * 256 + tid;
        if (i < NN) g_cnt[i] = 0;
        return;
    }
    int q = b - CLEAN_BLOCKS;
    int layer = q / 132;
    int r = q % 132;
    const float* Wl = W + (size_t)layer * 128 * 256;
    if (r < 128) {
        int k = tid;                       // 0..255
        int h = k >> 7, j = k & 127;
        float v = 0.5f * Wl[(size_t)j * 256 + h * 128 + r];
        __nv_bfloat16 hi = __float2bfloat16(v);
        g_Wh[layer][r * 256 + k] = hi;
        g_Wl[layer][r * 256 + k] = __float2bfloat16(v - __bfloat162float(hi));
    } else if (tid < 128) {
        int qq = r - 128;
        int h = qq & 1, typ = qq >> 1;     // 0 = src, 1 = dst
        const float* att = (typ ? adst : asrc) + layer * 256 + h * 128;
        const float* Wr  = Wl + (size_t)tid * 256 + h * 128;
        float sum = 0.f;
#pragma unroll 8
        for (int j = 0; j < 128; j++) sum += Wr[j] * att[j];
        (typ ? g_pd : g_ps)[layer][h * 128 + tid] = sum;
    }
}

// ---------------- fused alpha(layer0) + capacity-slotted scatter ------------
__device__ __forceinline__ void alpha_body(const float* __restrict__ x,
                                           int w, int lane) {
    float4 xv = *(const float4*)(x + (size_t)w * 128 + lane * 4);
    float4 p;
    p = *(const float4*)(&g_ps[0][lane * 4]);
    float s0 = xv.x * p.x + xv.y * p.y + xv.z * p.z + xv.w * p.w;
    p = *(const float4*)(&g_ps[0][128 + lane * 4]);
    float s1 = xv.x * p.x + xv.y * p.y + xv.z * p.z + xv.w * p.w;
    p = *(const float4*)(&g_pd[0][lane * 4]);
    float d0 = xv.x * p.x + xv.y * p.y + xv.z * p.z + xv.w * p.w;
    p = *(const float4*)(&g_pd[0][128 + lane * 4]);
    float d1 = xv.x * p.x + xv.y * p.y + xv.z * p.z + xv.w * p.w;
#pragma unroll
    for (int o = 16; o; o >>= 1) {
        s0 += __shfl_xor_sync(0xffffffffu, s0, o);
        s1 += __shfl_xor_sync(0xffffffffu, s1, o);
        d0 += __shfl_xor_sync(0xffffffffu, d0, o);
        d1 += __shfl_xor_sync(0xffffffffu, d1, o);
    }
    if (lane == 0) {
        g_as[w] = make_float2(s0, s1);
        g_ad[w] = make_float2(d0, d1);
    }
}

__global__ void __launch_bounds__(256) alpha_scatter_kernel(const float* __restrict__ x,
                                                            const int* __restrict__ ei) {
    int b = blockIdx.x;
    if (b < AGG_BLOCKS) {
        int w = (b * 256 + threadIdx.x) >> 5;
        if (w < NN) alpha_body(x, w, threadIdx.x & 31);
    } else {
        int i = (b - AGG_BLOCKS) * 256 + threadIdx.x;
        if (i >= EPE) return;
        int src, dst;
        if (i < EE) { src = ei[i]; dst = ei[EE + i]; }
        else        { src = i - EE; dst = i - EE; }
        src = min(max(src, 0), NN - 1);
        dst = min(max(dst, 0), NN - 1);
        int pos = atomicAdd(&g_cnt[dst], 1);
        if (pos < MAXDEG) g_srcs[(size_t)dst * MAXDEG + pos] = src;
    }
}

// ---------------- edge aggregation (warp per node, smem-staged weights) -----
__device__ __forceinline__ uint32_t pack_split(float a, float b, uint32_t& lo) {
    __nv_bfloat16 ha = __float2bfloat16(a), hb = __float2bfloat16(b);
    __nv_bfloat16 la = __float2bfloat16(a - __bfloat162float(ha));
    __nv_bfloat16 lb = __float2bfloat16(b - __bfloat162float(hb));
    lo = (uint32_t)__bfloat16_as_ushort(la) | ((uint32_t)__bfloat16_as_ushort(lb) << 16);
    return (uint32_t)__bfloat16_as_ushort(ha) | ((uint32_t)__bfloat16_as_ushort(hb) << 16);
}

__global__ void __launch_bounds__(256) aggregate_kernel(const float* __restrict__ x) {
    int node = (blockIdx.x * blockDim.x + threadIdx.x) >> 5;
    if (node >= NN) return;
    const int lane = threadIdx.x & 31;
    const int ww = (threadIdx.x >> 5) & 7;

    __shared__ __align__(16) float4 st_w[8][32];
    __shared__ int st_s[8][32];

    const int deg = min(g_cnt[node], MAXDEG);
    const int* srcs = g_srcs + (size_t)node * MAXDEG;
    const float2 adv = g_ad[node];

    float w0 = 0.f, w1 = 0.f;
    int sj = 0;
    if (lane < deg) {
        sj = srcs[lane];
        float2 a = g_as[sj];
        float e0 = a.x + adv.x;  e0 = e0 > 0.f ? e0 : 0.2f * e0;
        float e1 = a.y + adv.y;  e1 = e1 > 0.f ? e1 : 0.2f * e1;
        w0 = __expf(e0);
        w1 = __expf(e1);
    }
    float s0 = w0, s1 = w1;
    for (int e = 32 + lane; e < deg; e += 32) {
        float2 a = g_as[srcs[e]];
        float e0 = a.x + adv.x;  e0 = e0 > 0.f ? e0 : 0.2f * e0;
        float e1 = a.y + adv.y;  e1 = e1 > 0.f ? e1 : 0.2f * e1;
        s0 += __expf(e0);
        s1 += __expf(e1);
    }
#pragma unroll
    for (int o = 16; o; o >>= 1) {
        s0 += __shfl_xor_sync(0xffffffffu, s0, o);
        s1 += __shfl_xor_sync(0xffffffffu, s1, o);
    }

    ull a00 = 0ull, a01 = 0ull, a10 = 0ull, a11 = 0ull;
    const float* xb = x + lane * 4;

    for (int base = 0; base < deg; base += 32) {
        if (base) {                         // recompute only for deg>32 (rare)
            w0 = w1 = 0.f;
            sj = 0;
            if (base + lane < deg) {
                sj = srcs[base + lane];
                float2 a = g_as[sj];
                float e0 = a.x + adv.x;  e0 = e0 > 0.f ? e0 : 0.2f * e0;
                float e1 = a.y + adv.y;  e1 = e1 > 0.f ? e1 : 0.2f * e1;
                w0 = __expf(e0);
                w1 = __expf(e1);
            }
        }
        st_w[ww][lane] = make_float4(w0, w0, w1, w1);
        st_s[ww][lane] = sj;
        __syncwarp();
        int nn = min(32, deg - base);
#pragma unroll 2
        for (int i = 0; i < nn; i++) {
            int s = st_s[ww][i];
            F4U w; w.f = st_w[ww][i];
            F4U v; v.f = *(const float4*)(xb + (size_t)s * 128);
            fma2(a00, w.u.lo, v.u.lo);
            fma2(a01, w.u.lo, v.u.hi);
            fma2(a10, w.u.hi, v.u.lo);
            fma2(a11, w.u.hi, v.u.hi);
        }
        __syncwarp();
    }

    float i0 = 1.f / (s0 + 1e-16f);
    float i1 = 1.f / (s1 + 1e-16f);
    F4U r0, r1;
    r0.u.lo = a00; r0.u.hi = a01;
    r1.u.lo = a10; r1.u.hi = a11;

    uint2 h0, l0, h1, l1;
    h0.x = pack_split(r0.f.x * i0, r0.f.y * i0, l0.x);
    h0.y = pack_split(r0.f.z * i0, r0.f.w * i0, l0.y);
    h1.x = pack_split(r1.f.x * i1, r1.f.y * i1, l1.x);
    h1.y = pack_split(r1.f.z * i1, r1.f.w * i1, l1.y);
    size_t o = (size_t)node * 256 + lane * 4;
    *(uint2*)(g_ah + o)       = h0;
    *(uint2*)(g_al + o)       = l0;
    *(uint2*)(g_ah + o + 128) = h1;
    *(uint2*)(g_al + o + 128) = l1;
}

// ---------------- HMMA GEMM (cp.async double-buffered, M=128, padded) -------
// do_alpha=1 (gemm0): also computes next layer's alpha projections in the
// epilogue; per-wn partials go to unique smem slots (no atomics).
#define ROWB 80            /* smem row stride in bytes (32 bf16 + 16B pad) */
#define T_AH 0
#define T_AL 10240
#define T_BH 20480
#define T_BL 30720
#define BUFB 40960         /* one pipeline stage: 4 tiles */
#define OFF_SQ   (2 * BUFB)
#define OFF_P    (2 * BUFB + 512)
#define OFF_PART (2 * BUFB + 2560)        /* float[4][4][128] = 8192 B */
#define SMEM_GEMM (2 * BUFB + 2560 + 8192)

__device__ __forceinline__ void gemm_issue_load(uint32_t sb, int m0, int kc, int tid,
                                                const __nv_bfloat16* Wh,
                                                const __nv_bfloat16* Wl) {
#pragma unroll
    for (int it = 0; it < 2; it++) {
        int i = tid + it * 256;
        int r = i >> 2, kq = i & 3;
        uint32_t soff = (uint32_t)(r * ROWB + kq * 16);
        size_t ga = (size_t)(m0 + r) * 256 + kc * 32 + kq * 8;
        size_t gb = (size_t)r * 256 + kc * 32 + kq * 8;
        cpasync16(sb + T_AH + soff, g_ah + ga);
        cpasync16(sb + T_AL + soff, g_al + ga);
        cpasync16(sb + T_BH + soff, Wh + gb);
        cpasync16(sb + T_BL + soff, Wl + gb);
    }
}

__global__ void __launch_bounds__(256, 2) gemm_hmma_kernel(const float* __restrict__ bias,
                                                           float* __restrict__ out,
                                                           int layer, int do_alpha) {
    extern __shared__ __align__(16) char sm[];
    const int tid = threadIdx.x, lane = tid & 31, wid = tid >> 5;
    const int wm = wid >> 2, wn = wid & 3;     // warp grid 2 x 4
    const int m0 = blockIdx.x * 128;
    const uint32_t sbase = smem_u32(sm);
    const __nv_bfloat16* Wh = g_Wh[layer];
    const __nv_bfloat16* Wl = g_Wl[layer];

    float* sq   = (float*)(sm + OFF_SQ);
    float* pb   = (float*)(sm + OFF_P);     // [512]: ps(256), pd(256) for layer 1
    float* part = (float*)(sm + OFF_PART);  // [wn][4][128] unique-writer partials

    if (tid < 128) sq[tid] = 0.f;
    if (do_alpha) {
        pb[tid]       = g_ps[1][tid];
        pb[256 + tid] = g_pd[1][tid];
    }

    float acc[4][4][4];
#pragma unroll
    for (int a = 0; a < 4; a++)
#pragma unroll
        for (int b = 0; b < 4; b++)
#pragma unroll
            for (int c = 0; c < 4; c++) acc[a][b][c] = 0.f;

    const int rowselA = lane & 15, khA = (lane >> 4) & 1;
    const uint32_t offA = (uint32_t)((wm * 64 + rowselA) * ROWB + khA * 16);
    const int bnB = lane & 7, khB = (lane >> 3) & 1;
    const uint32_t offB = (uint32_t)((wn * 32 + bnB) * ROWB + khB * 16);

    gemm_issue_load(sbase, m0, 0, tid, Wh, Wl);
    CP_COMMIT();

    for (int kc = 0; kc < 8; kc++) {
        if (kc < 7) {
            gemm_issue_load(sbase + ((kc + 1) & 1) * BUFB, m0, kc + 1, tid, Wh, Wl);
            CP_COMMIT();
            asm volatile("cp.async.wait_group 1;" ::: "memory");
        } else {
            asm volatile("cp.async.wait_group 0;" ::: "memory");
        }
        __syncthreads();

        const uint32_t stg = sbase + (kc & 1) * BUFB;
#pragma unroll
        for (int s = 0; s < 2; s++) {
            uint32_t ah[4][4], al[4][4], bh[4][2], bl[4][2];
#pragma unroll
            for (int mi = 0; mi < 4; mi++) {
                uint32_t a = offA + (uint32_t)(mi * 16 * ROWB + s * 32);
                ldsm_x4(ah[mi], stg + T_AH + a);
                ldsm_x4(al[mi], stg + T_AL + a);
            }
#pragma unroll
            for (int nj = 0; nj < 4; nj++) {
                uint32_t b = offB + (uint32_t)(nj * 8 * ROWB + s * 32);
                ldsm_x2(bh[nj], stg + T_BH + b);
                ldsm_x2(bl[nj], stg + T_BL + b);
            }
#pragma unroll
            for (int mi = 0; mi < 4; mi++)
#pragma unroll
                for (int nj = 0; nj < 4; nj++) {
                    mma16816(acc[mi][nj], ah[mi], bh[nj]);
                    mma16816(acc[mi][nj], ah[mi], bl[nj]);
                    mma16816(acc[mi][nj], al[mi], bh[nj]);
                }
        }
        __syncthreads();
    }

    const int groupl = lane >> 2, qid = lane & 3;
    float2 bv[4];
#pragma unroll
    for (int nj = 0; nj < 4; nj++)
        bv[nj] = *(const float2*)(bias + wn * 32 + nj * 8 + qid * 2);

#pragma unroll
    for (int mi = 0; mi < 4; mi++) {
        float s1 = 0.f, s2 = 0.f;
#pragma unroll
        for (int nj = 0; nj < 4; nj++) {
            acc[mi][nj][0] += bv[nj].x;
            acc[mi][nj][1] += bv[nj].y;
            acc[mi][nj][2] += bv[nj].x;
            acc[mi][nj][3] += bv[nj].y;
            s1 += acc[mi][nj][0] * acc[mi][nj][0] + acc[mi][nj][1] * acc[mi][nj][1];
            s2 += acc[mi][nj][2] * acc[mi][nj][2] + acc[mi][nj][3] * acc[mi][nj][3];
        }
        s1 += __shfl_xor_sync(0xffffffffu, s1, 1);
        s1 += __shfl_xor_sync(0xffffffffu, s1, 2);
        s2 += __shfl_xor_sync(0xffffffffu, s2, 1);
        s2 += __shfl_xor_sync(0xffffffffu, s2, 2);
        if (qid == 0) {
            atomicAdd(&sq[wm * 64 + mi * 16 + groupl], s1);
            atomicAdd(&sq[wm * 64 + mi * 16 + groupl + 8], s2);
        }
    }
    __syncthreads();
    if (tid < 128) {
        float v = sq[tid];
        sq[tid] = 1.f / fmaxf(sqrtf(v), 1e-12f);
    }
    __syncthreads();

#pragma unroll
    for (int mi = 0; mi < 4; mi++) {
        int lr1 = wm * 64 + mi * 16 + groupl;
        int lr2 = lr1 + 8;
        float i1 = sq[lr1], i2 = sq[lr2];
        int r1 = m0 + lr1, r2 = m0 + lr2;
        float as0_1 = 0.f, as1_1 = 0.f, ad0_1 = 0.f, ad1_1 = 0.f;
        float as0_2 = 0.f, as1_2 = 0.f, ad0_2 = 0.f, ad1_2 = 0.f;
#pragma unroll
        for (int nj = 0; nj < 4; nj++) {
            int col = wn * 32 + nj * 8 + qid * 2;
            float v0 = acc[mi][nj][0] * i1, v1 = acc[mi][nj][1] * i1;
            float v2 = acc[mi][nj][2] * i2, v3 = acc[mi][nj][3] * i2;
            if (r1 < NN)
                *(float2*)(out + (size_t)r1 * 128 + col) = make_float2(v0, v1);
            if (r2 < NN)
                *(float2*)(out + (size_t)r2 * 128 + col) = make_float2(v2, v3);
            if (do_alpha) {
                float pa = pb[col],       pab = pb[col + 1];
                float qa = pb[128 + col], qab = pb[129 + col];
                float ra = pb[256 + col], rab = pb[257 + col];
                float ta = pb[384 + col], tab = pb[385 + col];
                as0_1 += pa * v0 + pab * v1;  as1_1 += qa * v0 + qab * v1;
                ad0_1 += ra * v0 + rab * v1;  ad1_1 += ta * v0 + tab * v1;
                as0_2 += pa * v2 + pab * v3;  as1_2 += qa * v2 + qab * v3;
                ad0_2 += ra * v2 + rab * v3;  ad1_2 += ta * v2 + tab * v3;
            }
        }
        if (do_alpha) {
#pragma unroll
            for (int o = 1; o < 4; o <<= 1) {
                as0_1 += __shfl_xor_sync(0xffffffffu, as0_1, o);
                as1_1 += __shfl_xor_sync(0xffffffffu, as1_1, o);
                ad0_1 += __shfl_xor_sync(0xffffffffu, ad0_1, o);
                ad1_1 += __shfl_xor_sync(0xffffffffu, ad1_1, o);
                as0_2 += __shfl_xor_sync(0xffffffffu, as0_2, o);
                as1_2 += __shfl_xor_sync(0xffffffffu, as1_2, o);
                ad0_2 += __shfl_xor_sync(0xffffffffu, ad0_2, o);
                ad1_2 += __shfl_xor_sync(0xffffffffu, ad1_2, o);
            }
            if (qid == 0) {
                float* p = part + wn * 512;   // unique (wn,row) writer: no atomics
                p[lr1]       = as0_1;  p[lr2]       = as0_2;
                p[128 + lr1] = as1_1;  p[128 + lr2] = as1_2;
                p[256 + lr1] = ad0_1;  p[256 + lr2] = ad0_2;
                p[384 + lr1] = ad1_1;  p[384 + lr2] = ad1_2;
            }
        }
    }
    if (do_alpha) {
        __syncthreads();
        if (tid < 128) {
            int row = m0 + tid;
            if (row < NN) {
                float as0 = part[tid]        + part[512 + tid]  + part[1024 + tid] + part[1536 + tid];
                float as1 = part[128 + tid]  + part[640 + tid]  + part[1152 + tid] + part[1664 + tid];
                float ad0 = part[256 + tid]  + part[768 + tid]  + part[1280 + tid] + part[1792 + tid];
                float ad1 = part[384 + tid]  + part[896 + tid]  + part[1408 + tid] + part[1920 + tid];
                g_as[row] = make_float2(as0, as1);
                g_ad[row] = make_float2(ad0, ad1);
            }
        }
    }
}

// ---------------- launch ----------------------------------------------------
extern "C" void kernel_launch(void* const* d_in, const int* in_sizes, int n_in,
                              void* d_out, int out_size) {
    const float* x    = (const float*)d_in[0];
    const int*   ei   = (const int*)d_in[1];
    const float* W    = (const float*)d_in[2];
    const float* asrc = (const float*)d_in[3];
    const float* adst = (const float*)d_in[4];
    const float* bias = (const float*)d_in[5];
    float*       out  = (float*)d_out;

    void* xbuf_p = nullptr;
    cudaGetSymbolAddress(&xbuf_p, g_xbuf);
    float* xbuf = (float*)xbuf_p;

    cudaFuncSetAttribute(gemm_hmma_kernel,
                         cudaFuncAttributeMaxDynamicSharedMemorySize, SMEM_GEMM);

    // slots: prep_clean=1, alpha_scatter=2, agg0=3, gemm0=4 (profiled, +alpha1),
    //        agg1=5, gemm1=6
    prep_clean_kernel<<<CLEAN_BLOCKS + 264, 256>>>(W, asrc, adst);
    alpha_scatter_kernel<<<AGG_BLOCKS + SCAT_BLOCKS, 256>>>(x, ei);
    aggregate_kernel<<<AGG_BLOCKS, 256>>>(x);
    gemm_hmma_kernel<<<TILES, 256, SMEM_GEMM>>>(bias, xbuf, 0, 1);

    aggregate_kernel<<<AGG_BLOCKS, 256>>>(xbuf);
    gemm_hmma_kernel<<<TILES, 256, SMEM_GEMM>>>(bias + 128, out, 1, 0);
}